// round 11
// baseline (speedup 1.0000x reference)
#include <cuda_runtime.h>
#include <cuda_fp16.h>
#include <math.h>

// ---------------------------------------------------------------------------
#define D_    2048
#define V_    2048
#define LSEQ  512
#define LP1   513
#define T_    65
#define G4    8192

#define NBLK  148
#define NT    1024
#define NW    32

#define JSM   13              // SMEM-resident h-elements per block (148*13 = 1924)
#define JL0   1924            // leftover j's 1924..2047 -> blocks 0..123
#define NJX   124

#define CANARY 0x7FC0DEADu    // NaN payload: never produced by real math

// dynamic smem layout (bytes)
#define OFF_H    (JSM * 4 * D_ * 2)           // 212992: h[2048] f32
#define OFF_PP   (OFF_H + D_ * 4)             // 221184: row params
#define OFF_XS   (OFF_PP + 896)               // 222080: xs[65][4]
#define OFF_RED  (OFF_XS + 1040)              // 223120: red[32]
#define SMEM_BYTES (OFF_RED + 144)            // 223264

// ---------------------------------------------------------------------------
__device__ __half g_w16[(size_t)V_ * D_];        // fp16 Wd rows (8 MB)
__device__ __half g_w16x[(size_t)NJX * 4 * D_];  // fp16 leftover gate rows
__device__ float g_enc[LP1 * V_];                // enc_proj
__device__ float g_hall[T_ * D_];                // h_t (poisoned, dataflow sync)
__device__ float g_dall[T_ * D_];                // d_t (poisoned, dataflow sync)
__device__ volatile unsigned g_arr[256];         // structural barrier slots
__device__ volatile unsigned g_rel;              // structural barrier release

// ---------------------------------------------------------------------------
// Structural grid barrier (2x per launch)
// ---------------------------------------------------------------------------
__device__ __forceinline__ void gridbar(unsigned gen) {
    __syncthreads();
    const int tid = threadIdx.x;
    if (tid == 0)
        asm volatile("st.release.gpu.global.u32 [%0], %1;"
                     :: "l"((void*)&g_arr[blockIdx.x]), "r"(gen) : "memory");
    if (blockIdx.x == 0) {
        if (tid < NBLK) {
            unsigned v;
            do {
                asm volatile("ld.acquire.gpu.global.u32 %0, [%1];"
                             : "=r"(v) : "l"((const void*)&g_arr[tid]) : "memory");
            } while ((int)(v - gen) < 0);
        }
        __syncthreads();
        if (tid == 0)
            asm volatile("st.release.gpu.global.u32 [%0], %1;"
                         :: "l"((void*)&g_rel), "r"(gen) : "memory");
    } else {
        if (tid == 0) {
            unsigned v;
            do {
                asm volatile("ld.acquire.gpu.global.u32 %0, [%1];"
                             : "=r"(v) : "l"((const void*)&g_rel) : "memory");
            } while ((int)(v - gen) < 0);
        }
        __syncthreads();
    }
}

// value poll: float4 with canary retry
__device__ __forceinline__ float4 poll4(const float* p) {
    unsigned x, y, z, w;
    asm volatile("ld.global.cg.v4.u32 {%0,%1,%2,%3}, [%4];"
                 : "=r"(x), "=r"(y), "=r"(z), "=r"(w) : "l"(p) : "memory");
    while (x == CANARY || y == CANARY || z == CANARY || w == CANARY) {
        __nanosleep(32);
        asm volatile("ld.global.cg.v4.u32 {%0,%1,%2,%3}, [%4];"
                     : "=r"(x), "=r"(y), "=r"(z), "=r"(w) : "l"(p) : "memory");
    }
    float4 r;
    r.x = __uint_as_float(x); r.y = __uint_as_float(y);
    r.z = __uint_as_float(z); r.w = __uint_as_float(w);
    return r;
}

// ---------------------------------------------------------------------------
// Branchless rational tanh (Eigen 13/6) + Newton reciprocal (no MUFU).
// ---------------------------------------------------------------------------
__device__ __forceinline__ float fast_tanh(float x) {
    float xc = fminf(fmaxf(x, -7.90531110763549805f), 7.90531110763549805f);
    float x2 = xc * xc;
    float p = -2.76076847742355e-16f;
    p = fmaf(p, x2, 2.00018790482477e-13f);
    p = fmaf(p, x2, -8.60467152213735e-11f);
    p = fmaf(p, x2, 5.12229709037114e-08f);
    p = fmaf(p, x2, 1.48572235717979e-05f);
    p = fmaf(p, x2, 6.37261928875436e-04f);
    p = fmaf(p, x2, 4.89352455891786e-03f);
    p *= xc;
    float q = 1.19825839466702e-06f;
    q = fmaf(q, x2, 1.18534705686654e-04f);
    q = fmaf(q, x2, 2.26843463243900e-03f);
    q = fmaf(q, x2, 4.89352518554385e-03f);
    float r = __uint_as_float(0x7EF311C3u - __float_as_uint(q));
    r = r * fmaf(-q, r, 2.0f);
    r = r * fmaf(-q, r, 2.0f);
    r = r * fmaf(-q, r, 2.0f);
    return p * r;
}
__device__ __forceinline__ float hw_tanh(float x) {
    float y;
    asm("tanh.approx.f32 %0, %1;" : "=f"(y) : "f"(x));
    return y;
}

// fp16 dot helpers
__device__ __forceinline__ float dot8(uint4 u, float4 ha, float4 hb, float acc) {
    float2 f0 = __half22float2(*(__half2*)&u.x);
    float2 f1 = __half22float2(*(__half2*)&u.y);
    float2 f2 = __half22float2(*(__half2*)&u.z);
    float2 f3 = __half22float2(*(__half2*)&u.w);
    acc = fmaf(f0.x, ha.x, acc);
    acc = fmaf(f0.y, ha.y, acc);
    acc = fmaf(f1.x, ha.z, acc);
    acc = fmaf(f1.y, ha.w, acc);
    acc = fmaf(f2.x, hb.x, acc);
    acc = fmaf(f2.y, hb.y, acc);
    acc = fmaf(f3.x, hb.z, acc);
    acc = fmaf(f3.y, hb.w, acc);
    return acc;
}
__device__ __forceinline__ float dot4h(uint2 u, float4 h, float acc) {
    float2 f0 = __half22float2(*(__half2*)&u.x);
    float2 f1 = __half22float2(*(__half2*)&u.y);
    acc = fmaf(f0.x, h.x, acc);
    acc = fmaf(f0.y, h.y, acc);
    acc = fmaf(f1.x, h.z, acc);
    acc = fmaf(f1.y, h.w, acc);
    return acc;
}

// mma.sync m16n8k16 row.col f32.f16.f16.f32
__device__ __forceinline__ void mma16816(float* c, const unsigned* a, const unsigned* b) {
    asm volatile(
        "mma.sync.aligned.m16n8k16.row.col.f32.f16.f16.f32 "
        "{%0,%1,%2,%3}, {%4,%5,%6,%7}, {%8,%9}, {%0,%1,%2,%3};"
        : "+f"(c[0]), "+f"(c[1]), "+f"(c[2]), "+f"(c[3])
        : "r"(a[0]), "r"(a[1]), "r"(a[2]), "r"(a[3]), "r"(b[0]), "r"(b[1]));
}

#define KS 40

__global__ void __launch_bounds__(NT, 1)
decoder_kernel(const float* __restrict__ initial_state,
               const float* __restrict__ enc_states,
               const float* __restrict__ seq_points,
               const int*   __restrict__ positions,
               const float* __restrict__ W_ih,
               const float* __restrict__ W_hh,
               const float* __restrict__ b_ih,
               const float* __restrict__ b_hh,
               const float* __restrict__ We_w,
               const float* __restrict__ We_b,
               const float* __restrict__ Wd_w,
               const float* __restrict__ Wd_b,
               const float* __restrict__ v_w,
               const float* __restrict__ v_b,
               float* __restrict__ out_logits,
               float* __restrict__ out_hs,
               float* __restrict__ out_losses)
{
    extern __shared__ __align__(16) char dynsm[];
    __half* wsm = (__half*)dynsm;
    float*  hsm = (float*)(dynsm + OFF_H);
    float*  pp  = (float*)(dynsm + OFF_PP);
    float*  xs  = (float*)(dynsm + OFF_XS);
    float*  red = (float*)(dynsm + OFF_RED);

    const int tid  = threadIdx.x;
    const int wid  = tid >> 5;
    const int lane = tid & 31;
    const int b    = blockIdx.x;

    unsigned gen = g_rel;

    // =======================================================================
    // Phase G: enc_proj GEMM on tensor cores (blocks 0..79)
    // =======================================================================
    if (b < 80) {
        __half* ga = (__half*)dynsm;
        __half* gb = ga + 128 * KS;
        const int l0 = (b / 16) * 128;
        const int v0 = (b % 16) * 128;
        const int warpM = wid >> 3;
        const int warpN = wid & 7;
        const int g  = lane >> 2;
        const int t2 = (lane & 3) * 2;
        const int ldrow = tid >> 3;
        const int ldk   = (tid & 7) * 4;

        float c[2][2][4];
        #pragma unroll
        for (int m = 0; m < 2; ++m)
            #pragma unroll
            for (int n = 0; n < 2; ++n)
                #pragma unroll
                for (int q = 0; q < 4; ++q) c[m][n][q] = 0.f;

        for (int k0 = 0; k0 < D_; k0 += 32) {
            int gl = l0 + ldrow; if (gl > 512) gl = 512;
            float4 av = *(const float4*)&enc_states[(size_t)gl * D_ + k0 + ldk];
            float4 bv = *(const float4*)&We_w[(size_t)(v0 + ldrow) * D_ + k0 + ldk];
            __syncthreads();
            *(__half2*)&ga[ldrow * KS + ldk]     = __floats2half2_rn(av.x, av.y);
            *(__half2*)&ga[ldrow * KS + ldk + 2] = __floats2half2_rn(av.z, av.w);
            *(__half2*)&gb[ldrow * KS + ldk]     = __floats2half2_rn(bv.x, bv.y);
            *(__half2*)&gb[ldrow * KS + ldk + 2] = __floats2half2_rn(bv.z, bv.w);
            __syncthreads();

            #pragma unroll
            for (int ks = 0; ks < 2; ++ks) {
                const int kb = ks * 16;
                unsigned a[2][4], bb[2][2];
                #pragma unroll
                for (int m = 0; m < 2; ++m) {
                    int ar = warpM * 32 + m * 16;
                    a[m][0] = *(const unsigned*)&ga[(ar + g) * KS + kb + t2];
                    a[m][1] = *(const unsigned*)&ga[(ar + g + 8) * KS + kb + t2];
                    a[m][2] = *(const unsigned*)&ga[(ar + g) * KS + kb + t2 + 8];
                    a[m][3] = *(const unsigned*)&ga[(ar + g + 8) * KS + kb + t2 + 8];
                }
                #pragma unroll
                for (int n = 0; n < 2; ++n) {
                    int br = warpN * 16 + n * 8;
                    bb[n][0] = *(const unsigned*)&gb[(br + g) * KS + kb + t2];
                    bb[n][1] = *(const unsigned*)&gb[(br + g) * KS + kb + t2 + 8];
                }
                #pragma unroll
                for (int m = 0; m < 2; ++m)
                    #pragma unroll
                    for (int n = 0; n < 2; ++n)
                        mma16816(c[m][n], a[m], bb[n]);
            }
        }

        #pragma unroll
        for (int m = 0; m < 2; ++m) {
            #pragma unroll
            for (int n = 0; n < 2; ++n) {
                int lrow = l0 + warpM * 32 + m * 16 + g;
                int vcol = v0 + warpN * 16 + n * 8 + t2;
                if (lrow < LP1) {
                    g_enc[(size_t)lrow * V_ + vcol]     = c[m][n][0] + We_b[vcol];
                    g_enc[(size_t)lrow * V_ + vcol + 1] = c[m][n][1] + We_b[vcol + 1];
                }
                if (lrow + 8 < LP1) {
                    g_enc[(size_t)(lrow + 8) * V_ + vcol]     = c[m][n][2] + We_b[vcol];
                    g_enc[(size_t)(lrow + 8) * V_ + vcol + 1] = c[m][n][3] + We_b[vcol + 1];
                }
            }
        }
        __syncthreads();
    }

    // =======================================================================
    // Prologue A: own 52 gate rows -> SMEM fp16
    // =======================================================================
    {
        const int n4 = JSM * 4 * (D_ / 4);
        for (int i = tid; i < n4; i += NT) {
            int rr = i >> 9;
            int k4 = i & 511;
            int lj = rr >> 2, gate = rr & 3;
            const float4* src = (const float4*)&W_hh[(size_t)(gate * D_ + b * JSM + lj) * D_] + k4;
            float4 v = *src;
            __half2 h01 = __floats2half2_rn(v.x, v.y);
            __half2 h23 = __floats2half2_rn(v.z, v.w);
            uint2 pk; pk.x = *(unsigned*)&h01; pk.y = *(unsigned*)&h23;
            ((uint2*)wsm)[(size_t)rr * 512 + k4] = pk;
        }
    }
    if (tid < 56) {
        int lj = tid >> 2, gate = tid & 3;
        int j = (lj < JSM) ? (b * JSM + lj) : (JL0 + b);
        if (lj < JSM || b < NJX) {
            int r = gate * D_ + j;
            pp[tid * 4 + 0] = b_ih[r] + b_hh[r];
            pp[tid * 4 + 1] = W_ih[r * 3 + 0];
            pp[tid * 4 + 2] = W_ih[r * 3 + 1];
            pp[tid * 4 + 3] = W_ih[r * 3 + 2];
        }
    }
    if (tid < T_) {
        float x0 = 0.f, x1 = 0.f, x2 = 1.f;
        if (tid >= 1) {
            int pos = positions[tid - 1];
            x0 = seq_points[pos * 3 + 0];
            x1 = seq_points[pos * 3 + 1];
            x2 = seq_points[pos * 3 + 2];
        }
        xs[tid * 4 + 0] = x0; xs[tid * 4 + 1] = x1; xs[tid * 4 + 2] = x2;
    }
    // Prologue B (blocks 80..147): Wd + leftover gate rows -> fp16 L2 buffers
    if (b >= 80) {
        const int nWd = V_ * (D_ / 4);
        const int nX  = NJX * 4 * (D_ / 4);
        for (int i = (b - 80) * NT + tid; i < nWd + nX; i += (NBLK - 80) * NT) {
            float4 v; uint2* dst;
            if (i < nWd) {
                v = ((const float4*)Wd_w)[i];
                dst = (uint2*)g_w16 + i;
            } else {
                int ii = i - nWd;
                int flat = ii >> 9;
                int k4 = ii & 511;
                int jj = flat >> 2, gate = flat & 3;
                v = *((const float4*)&W_hh[(size_t)(gate * D_ + JL0 + jj) * D_] + k4);
                dst = (uint2*)g_w16x + ii;
            }
            __half2 h01 = __floats2half2_rn(v.x, v.y);
            __half2 h23 = __floats2half2_rn(v.z, v.w);
            uint2 pk; pk.x = *(unsigned*)&h01; pk.y = *(unsigned*)&h23;
            *dst = pk;
        }
    }
    // Prologue C (blocks 0..79): poison h and d buffers
    if (b < 80) {
        unsigned* hh = (unsigned*)g_hall;
        unsigned* dd = (unsigned*)g_dall;
        for (int i = b * NT + tid; i < T_ * D_; i += 80 * NT) {
            hh[i] = CANARY;
            dd[i] = CANARY;
        }
    }

    hsm[tid]      = initial_state[tid];
    hsm[tid + NT] = initial_state[tid + NT];
    gridbar(++gen);

    // =======================================================================
    // Stage 1 + shadow: warps 0..7 recurrence; 8..9 d-crew; 10..31 logits crew
    // =======================================================================
    if (wid < 8) {
        // ---- recurrence producers ----
        const int njs = (wid < 6) ? 2 : ((wid == 6) ? 1 : ((b < NJX) ? 1 : 0));
        const int lj0 = (wid < 6) ? 2 * wid : ((wid == 6) ? 12 : 13);
        float cst[2] = {0.f, 0.f};

        for (int t = 0; t < T_; ++t) {
            if (njs) {
                const float4* h4 = (const float4*)hsm;
                const float x0 = xs[t * 4 + 0], x1 = xs[t * 4 + 1], x2 = xs[t * 4 + 2];

                #pragma unroll
                for (int jj = 0; jj < 2; ++jj) {
                    if (jj >= njs) break;
                    const int lj = lj0 + jj;
                    float acc[4] = {0.f, 0.f, 0.f, 0.f};

                    if (wid < 7) {
                        const uint4* w0 = (const uint4*)wsm + (size_t)(lj * 4) * 256;
                        #pragma unroll 2
                        for (int k8 = lane; k8 < 256; k8 += 32) {
                            float4 ha = h4[2 * k8];
                            float4 hb = h4[2 * k8 + 1];
                            acc[0] = dot8(w0[k8], ha, hb, acc[0]);
                            acc[1] = dot8(w0[256 + k8], ha, hb, acc[1]);
                            acc[2] = dot8(w0[512 + k8], ha, hb, acc[2]);
                            acc[3] = dot8(w0[768 + k8], ha, hb, acc[3]);
                        }
                    } else {
                        const uint4* w0 = (const uint4*)g_w16x + (size_t)(b * 4) * 256;
                        #pragma unroll 2
                        for (int k8 = lane; k8 < 256; k8 += 32) {
                            float4 ha = h4[2 * k8];
                            float4 hb = h4[2 * k8 + 1];
                            acc[0] = dot8(__ldcg(w0 + k8), ha, hb, acc[0]);
                            acc[1] = dot8(__ldcg(w0 + 256 + k8), ha, hb, acc[1]);
                            acc[2] = dot8(__ldcg(w0 + 512 + k8), ha, hb, acc[2]);
                            acc[3] = dot8(__ldcg(w0 + 768 + k8), ha, hb, acc[3]);
                        }
                    }
                    #pragma unroll
                    for (int off = 16; off > 0; off >>= 1) {
                        acc[0] += __shfl_xor_sync(0xffffffffu, acc[0], off);
                        acc[1] += __shfl_xor_sync(0xffffffffu, acc[1], off);
                        acc[2] += __shfl_xor_sync(0xffffffffu, acc[2], off);
                        acc[3] += __shfl_xor_sync(0xffffffffu, acc[3], off);
                    }
                    const int gsel = lane & 3;
                    const float* P = pp + (lj * 4 + gsel) * 4;
                    float e = P[0] + P[1] * x0 + P[2] * x1 + P[3] * x2;
                    float z = ((gsel == 0) ? acc[0] : (gsel == 1) ? acc[1]
                             : (gsel == 2) ? acc[2] : acc[3]) + e;
                    bool isG = (gsel == 2);
                    float arg = isG ? z : 0.5f * z;
                    float yt  = fast_tanh(arg);
                    float y   = isG ? yt : fmaf(0.5f, yt, 0.5f);
                    float i_ = __shfl_sync(0xffffffffu, y, 0);
                    float f_ = __shfl_sync(0xffffffffu, y, 1);
                    float g_ = __shfl_sync(0xffffffffu, y, 2);
                    float o_ = __shfl_sync(0xffffffffu, y, 3);
                    cst[jj] = fmaf(f_, cst[jj], i_ * g_);
                    float h = o_ * fast_tanh(cst[jj]);
                    if (lane == 0) {
                        int jglob = (wid < 7) ? (b * JSM + lj) : (JL0 + b);
                        asm volatile("st.global.cg.f32 [%0], %1;"
                            :: "l"(&g_hall[(size_t)t * D_ + jglob]), "f"(h) : "memory");
                    }
                }
            }
            asm volatile("bar.sync 1, 256;" ::: "memory");   // hsm reads done

            // gather h_t: 8 values per thread (tid < 256)
            {
                const float* hb = g_hall + (size_t)t * D_ + tid * 8;
                float4 v0 = poll4(hb);
                float4 v1 = poll4(hb + 4);
                ((float4*)hsm)[tid * 2]     = v0;
                ((float4*)hsm)[tid * 2 + 1] = v1;
                if (b == t) {
                    // out_hs is only 4-byte aligned (odd float offset into d_out):
                    // MUST use scalar stores here.
                    float* op = out_hs + (size_t)t * D_ + tid * 8;
                    op[0] = v0.x; op[1] = v0.y; op[2] = v0.z; op[3] = v0.w;
                    op[4] = v1.x; op[5] = v1.y; op[6] = v1.z; op[7] = v1.w;
                }
            }
            asm volatile("bar.sync 1, 256;" ::: "memory");   // hsm ready
        }
    } else if (wid < 10) {
        // ---- d-crew: d_t[v] for this block's 13(+1) v's ----
        int vj[7], nd;
        if (wid == 8) {
            nd = 7;
            #pragma unroll
            for (int r = 0; r < 7; ++r) vj[r] = b * JSM + r;
        } else {
            nd = (b < NJX) ? 7 : 6;
            #pragma unroll
            for (int r = 0; r < 6; ++r) vj[r] = b * JSM + 7 + r;
            vj[6] = JL0 + b;
        }
        float wdb[7];
        #pragma unroll
        for (int r = 0; r < 7; ++r) wdb[r] = (r < nd) ? Wd_b[vj[r]] : 0.f;

        for (int t = 0; t < T_; ++t) {
            const float* hp = g_hall + (size_t)t * D_;
            float acc[7] = {0.f, 0.f, 0.f, 0.f, 0.f, 0.f, 0.f};
            #pragma unroll 2
            for (int i = 0; i < 16; ++i) {
                int k4 = lane + i * 32;
                float4 h = poll4(hp + k4 * 4);
                #pragma unroll
                for (int r = 0; r < 7; ++r) {
                    if (r < nd) {
                        uint2 w = __ldcg((const uint2*)(g_w16 + (size_t)vj[r] * D_) + k4);
                        acc[r] = dot4h(w, h, acc[r]);
                    }
                }
            }
            #pragma unroll
            for (int off = 16; off > 0; off >>= 1) {
                #pragma unroll
                for (int r = 0; r < 7; ++r)
                    acc[r] += __shfl_xor_sync(0xffffffffu, acc[r], off);
            }
            if (lane < nd) {
                float v = acc[0];
                if (lane == 1) v = acc[1];
                if (lane == 2) v = acc[2];
                if (lane == 3) v = acc[3];
                if (lane == 4) v = acc[4];
                if (lane == 5) v = acc[5];
                if (lane == 6) v = acc[6];
                float wb = wdb[0];
                if (lane == 1) wb = wdb[1];
                if (lane == 2) wb = wdb[2];
                if (lane == 3) wb = wdb[3];
                if (lane == 4) wb = wdb[4];
                if (lane == 5) wb = wdb[5];
                if (lane == 6) wb = wdb[6];
                int v_ = vj[0];
                if (lane == 1) v_ = vj[1];
                if (lane == 2) v_ = vj[2];
                if (lane == 3) v_ = vj[3];
                if (lane == 4) v_ = vj[4];
                if (lane == 5) v_ = vj[5];
                if (lane == 6) v_ = vj[6];
                asm volatile("st.global.cg.f32 [%0], %1;"
                    :: "l"(&g_dall[(size_t)t * D_ + v_]), "f"(v + wb) : "memory");
            }
        }
    } else {
        // ---- logits crew: items (t, rl) -> row l = b + rl*148 ----
        const float vb = v_b[0];
        for (int idx = wid - 10; idx < T_ * 4; idx += 22) {
            int t  = idx >> 2;
            int rl = idx & 3;
            int l  = b + rl * 148;
            if (l >= LP1) continue;
            const float* dp = g_dall + (size_t)t * D_;
            const float4* ep = (const float4*)(g_enc + (size_t)l * V_);
            const float4* wp = (const float4*)v_w;
            float acc = 0.f;
            #pragma unroll 2
            for (int i = 0; i < 16; ++i) {
                int k4 = lane + i * 32;
                float4 d = poll4(dp + k4 * 4);
                float4 e = __ldg(ep + k4);
                float4 w = __ldg(wp + k4);
                acc = fmaf(hw_tanh(e.x + d.x), w.x, acc);
                acc = fmaf(hw_tanh(e.y + d.y), w.y, acc);
                acc = fmaf(hw_tanh(e.z + d.z), w.z, acc);
                acc = fmaf(hw_tanh(e.w + d.w), w.w, acc);
            }
            #pragma unroll
            for (int off = 16; off > 0; off >>= 1)
                acc += __shfl_down_sync(0xffffffffu, acc, off);
            if (lane == 0)
                __stcg(&out_logits[(size_t)t * LP1 + l], acc + vb);
        }
    }

    gridbar(++gen);     // everything published

    // =======================================================================
    // Stage 3: losses
    // =======================================================================
    if (b < T_) {
        const int t = b;
        const float* lg = out_logits + (size_t)t * LP1;

        float m = -1e30f;
        for (int i = tid; i < LP1; i += NT) m = fmaxf(m, __ldcg(lg + i));
        #pragma unroll
        for (int off = 16; off > 0; off >>= 1)
            m = fmaxf(m, __shfl_down_sync(0xffffffffu, m, off));
        if (lane == 0) red[wid] = m;
        __syncthreads();
        if (wid == 0) {
            float mm = (lane < NW) ? red[lane] : -1e30f;
            #pragma unroll
            for (int off = 16; off > 0; off >>= 1)
                mm = fmaxf(mm, __shfl_down_sync(0xffffffffu, mm, off));
            if (lane == 0) red[0] = mm;
        }
        __syncthreads();
        m = red[0];
        __syncthreads();

        float s = 0.f;
        for (int i = tid; i < LP1; i += NT) s += expf(__ldcg(lg + i) - m);
        #pragma unroll
        for (int off = 16; off > 0; off >>= 1)
            s += __shfl_down_sync(0xffffffffu, s, off);
        if (lane == 0) red[wid] = s;
        __syncthreads();
        if (wid == 0) {
            float ss = (lane < NW) ? red[lane] : 0.f;
            #pragma unroll
            for (int off = 16; off > 0; off >>= 1)
                ss += __shfl_down_sync(0xffffffffu, ss, off);
            if (lane == 0) {
                int tgt = (t < 64) ? positions[t] : LSEQ;
                out_losses[t] = m + logf(ss) - __ldcg(lg + tgt);
            }
        }
    }
}

// ---------------------------------------------------------------------------
extern "C" void kernel_launch(void* const* d_in, const int* in_sizes, int n_in,
                              void* d_out, int out_size) {
    const float* initial_state = (const float*)d_in[0];
    const float* enc_states    = (const float*)d_in[1];
    const float* seq_points    = (const float*)d_in[2];
    const int*   positions     = (const int*)  d_in[3];
    const float* W_ih          = (const float*)d_in[4];
    const float* W_hh          = (const float*)d_in[5];
    const float* b_ih          = (const float*)d_in[6];
    const float* b_hh          = (const float*)d_in[7];
    const float* We_w          = (const float*)d_in[8];
    const float* We_b          = (const float*)d_in[9];
    const float* Wd_w          = (const float*)d_in[10];
    const float* Wd_b          = (const float*)d_in[11];
    const float* v_w           = (const float*)d_in[12];
    const float* v_b           = (const float*)d_in[13];

    float* out        = (float*)d_out;
    float* out_logits = out;
    float* out_hs     = out + T_ * LP1;
    float* out_losses = out + T_ * LP1 + T_ * D_;

    static int smem_set = 0;
    if (!smem_set) {
        cudaFuncSetAttribute(decoder_kernel,
                             cudaFuncAttributeMaxDynamicSharedMemorySize, SMEM_BYTES);
        smem_set = 1;
    }

    decoder_kernel<<<NBLK, NT, SMEM_BYTES>>>(
        initial_state, enc_states, seq_points, positions,
        W_ih, W_hh, b_ih, b_hh, We_w, We_b, Wd_w, Wd_b,
        v_w, v_b, out_logits, out_hs, out_losses);
}

// round 12
// speedup vs baseline: 1.6262x; 1.6262x over previous
#include <cuda_runtime.h>
#include <cuda_fp16.h>
#include <math.h>

// ---------------------------------------------------------------------------
#define D_    2048
#define V_    2048
#define LSEQ  512
#define LP1   513
#define T_    65
#define G4    8192

#define NBLK  148
#define NT    1024
#define NW    32

#define JSM   13              // SMEM-resident h-elements per block (148*13 = 1924)
#define JL0   1924            // leftover j's 1924..2047 -> blocks 0..123
#define NJX   124

#define CANARY 0x7FC0DEADu    // NaN payload: never produced by real math

// dynamic smem layout (bytes)
#define OFF_H    (JSM * 4 * D_ * 2)           // 212992: h[2048] f32
#define OFF_PP   (OFF_H + D_ * 4)             // 221184: row params
#define OFF_XS   (OFF_PP + 896)               // 222080: xs[65][4]
#define OFF_RED  (OFF_XS + 1040)              // 223120: red[32] (+leftover z[4])
#define SMEM_BYTES (OFF_RED + 144)            // 223264

// ---------------------------------------------------------------------------
__device__ __half g_w16[(size_t)V_ * D_];        // fp16 Wd rows (8 MB)
__device__ __half g_w16x[(size_t)NJX * 4 * D_];  // fp16 leftover gate rows
__device__ float g_enc[LP1 * V_];                // enc_proj
__device__ float g_hall[T_ * D_];                // h_t (poisoned, dataflow sync)
__device__ float g_dall[T_ * D_];                // d_t (ready at gridbar, no poison)
__device__ volatile unsigned g_arr[256];         // structural barrier slots
__device__ volatile unsigned g_rel;              // structural barrier release

// ---------------------------------------------------------------------------
// Structural grid barrier
// ---------------------------------------------------------------------------
__device__ __forceinline__ void gridbar(unsigned gen) {
    __syncthreads();
    const int tid = threadIdx.x;
    if (tid == 0)
        asm volatile("st.release.gpu.global.u32 [%0], %1;"
                     :: "l"((void*)&g_arr[blockIdx.x]), "r"(gen) : "memory");
    if (blockIdx.x == 0) {
        if (tid < NBLK) {
            unsigned v;
            do {
                asm volatile("ld.acquire.gpu.global.u32 %0, [%1];"
                             : "=r"(v) : "l"((const void*)&g_arr[tid]) : "memory");
            } while ((int)(v - gen) < 0);
        }
        __syncthreads();
        if (tid == 0)
            asm volatile("st.release.gpu.global.u32 [%0], %1;"
                         :: "l"((void*)&g_rel), "r"(gen) : "memory");
    } else {
        if (tid == 0) {
            unsigned v;
            do {
                asm volatile("ld.acquire.gpu.global.u32 %0, [%1];"
                             : "=r"(v) : "l"((const void*)&g_rel) : "memory");
            } while ((int)(v - gen) < 0);
        }
        __syncthreads();
    }
}

// ---------------------------------------------------------------------------
// Branchless rational tanh (Eigen 13/6) + Newton reciprocal (no MUFU).
// ---------------------------------------------------------------------------
__device__ __forceinline__ float fast_tanh(float x) {
    float xc = fminf(fmaxf(x, -7.90531110763549805f), 7.90531110763549805f);
    float x2 = xc * xc;
    float p = -2.76076847742355e-16f;
    p = fmaf(p, x2, 2.00018790482477e-13f);
    p = fmaf(p, x2, -8.60467152213735e-11f);
    p = fmaf(p, x2, 5.12229709037114e-08f);
    p = fmaf(p, x2, 1.48572235717979e-05f);
    p = fmaf(p, x2, 6.37261928875436e-04f);
    p = fmaf(p, x2, 4.89352455891786e-03f);
    p *= xc;
    float q = 1.19825839466702e-06f;
    q = fmaf(q, x2, 1.18534705686654e-04f);
    q = fmaf(q, x2, 2.26843463243900e-03f);
    q = fmaf(q, x2, 4.89352518554385e-03f);
    float r = __uint_as_float(0x7EF311C3u - __float_as_uint(q));
    r = r * fmaf(-q, r, 2.0f);
    r = r * fmaf(-q, r, 2.0f);
    r = r * fmaf(-q, r, 2.0f);
    return p * r;
}
__device__ __forceinline__ float hw_tanh(float x) {
    float y;
    asm("tanh.approx.f32 %0, %1;" : "=f"(y) : "f"(x));
    return y;
}

// fp16 dot helpers
__device__ __forceinline__ float dot8(uint4 u, float4 ha, float4 hb, float acc) {
    float2 f0 = __half22float2(*(__half2*)&u.x);
    float2 f1 = __half22float2(*(__half2*)&u.y);
    float2 f2 = __half22float2(*(__half2*)&u.z);
    float2 f3 = __half22float2(*(__half2*)&u.w);
    acc = fmaf(f0.x, ha.x, acc);
    acc = fmaf(f0.y, ha.y, acc);
    acc = fmaf(f1.x, ha.z, acc);
    acc = fmaf(f1.y, ha.w, acc);
    acc = fmaf(f2.x, hb.x, acc);
    acc = fmaf(f2.y, hb.y, acc);
    acc = fmaf(f3.x, hb.z, acc);
    acc = fmaf(f3.y, hb.w, acc);
    return acc;
}
__device__ __forceinline__ float dot4h(uint2 u, float4 h, float acc) {
    float2 f0 = __half22float2(*(__half2*)&u.x);
    float2 f1 = __half22float2(*(__half2*)&u.y);
    acc = fmaf(f0.x, h.x, acc);
    acc = fmaf(f0.y, h.y, acc);
    acc = fmaf(f1.x, h.z, acc);
    acc = fmaf(f1.y, h.w, acc);
    return acc;
}

// mma.sync m16n8k16 row.col f32.f16.f16.f32
__device__ __forceinline__ void mma16816(float* c, const unsigned* a, const unsigned* b) {
    asm volatile(
        "mma.sync.aligned.m16n8k16.row.col.f32.f16.f16.f32 "
        "{%0,%1,%2,%3}, {%4,%5,%6,%7}, {%8,%9}, {%0,%1,%2,%3};"
        : "+f"(c[0]), "+f"(c[1]), "+f"(c[2]), "+f"(c[3])
        : "r"(a[0]), "r"(a[1]), "r"(a[2]), "r"(a[3]), "r"(b[0]), "r"(b[1]));
}

#define KS 40

__global__ void __launch_bounds__(NT, 1)
decoder_kernel(const float* __restrict__ initial_state,
               const float* __restrict__ enc_states,
               const float* __restrict__ seq_points,
               const int*   __restrict__ positions,
               const float* __restrict__ W_ih,
               const float* __restrict__ W_hh,
               const float* __restrict__ b_ih,
               const float* __restrict__ b_hh,
               const float* __restrict__ We_w,
               const float* __restrict__ We_b,
               const float* __restrict__ Wd_w,
               const float* __restrict__ Wd_b,
               const float* __restrict__ v_w,
               const float* __restrict__ v_b,
               float* __restrict__ out_logits,
               float* __restrict__ out_hs,
               float* __restrict__ out_losses)
{
    extern __shared__ __align__(16) char dynsm[];
    __half* wsm = (__half*)dynsm;
    float*  hsm = (float*)(dynsm + OFF_H);
    float*  pp  = (float*)(dynsm + OFF_PP);
    float*  xs  = (float*)(dynsm + OFF_XS);
    float*  red = (float*)(dynsm + OFF_RED);

    const int tid  = threadIdx.x;
    const int wid  = tid >> 5;
    const int lane = tid & 31;
    const int b    = blockIdx.x;

    unsigned gen = g_rel;

    // =======================================================================
    // Phase G: enc_proj GEMM on tensor cores (blocks 0..79)
    // =======================================================================
    if (b < 80) {
        __half* ga = (__half*)dynsm;
        __half* gb = ga + 128 * KS;
        const int l0 = (b / 16) * 128;
        const int v0 = (b % 16) * 128;
        const int warpM = wid >> 3;
        const int warpN = wid & 7;
        const int g  = lane >> 2;
        const int t2 = (lane & 3) * 2;
        const int ldrow = tid >> 3;
        const int ldk   = (tid & 7) * 4;

        float c[2][2][4];
        #pragma unroll
        for (int m = 0; m < 2; ++m)
            #pragma unroll
            for (int n = 0; n < 2; ++n)
                #pragma unroll
                for (int q = 0; q < 4; ++q) c[m][n][q] = 0.f;

        for (int k0 = 0; k0 < D_; k0 += 32) {
            int gl = l0 + ldrow; if (gl > 512) gl = 512;
            float4 av = *(const float4*)&enc_states[(size_t)gl * D_ + k0 + ldk];
            float4 bv = *(const float4*)&We_w[(size_t)(v0 + ldrow) * D_ + k0 + ldk];
            __syncthreads();
            *(__half2*)&ga[ldrow * KS + ldk]     = __floats2half2_rn(av.x, av.y);
            *(__half2*)&ga[ldrow * KS + ldk + 2] = __floats2half2_rn(av.z, av.w);
            *(__half2*)&gb[ldrow * KS + ldk]     = __floats2half2_rn(bv.x, bv.y);
            *(__half2*)&gb[ldrow * KS + ldk + 2] = __floats2half2_rn(bv.z, bv.w);
            __syncthreads();

            #pragma unroll
            for (int ks = 0; ks < 2; ++ks) {
                const int kb = ks * 16;
                unsigned a[2][4], bb[2][2];
                #pragma unroll
                for (int m = 0; m < 2; ++m) {
                    int ar = warpM * 32 + m * 16;
                    a[m][0] = *(const unsigned*)&ga[(ar + g) * KS + kb + t2];
                    a[m][1] = *(const unsigned*)&ga[(ar + g + 8) * KS + kb + t2];
                    a[m][2] = *(const unsigned*)&ga[(ar + g) * KS + kb + t2 + 8];
                    a[m][3] = *(const unsigned*)&ga[(ar + g + 8) * KS + kb + t2 + 8];
                }
                #pragma unroll
                for (int n = 0; n < 2; ++n) {
                    int br = warpN * 16 + n * 8;
                    bb[n][0] = *(const unsigned*)&gb[(br + g) * KS + kb + t2];
                    bb[n][1] = *(const unsigned*)&gb[(br + g) * KS + kb + t2 + 8];
                }
                #pragma unroll
                for (int m = 0; m < 2; ++m)
                    #pragma unroll
                    for (int n = 0; n < 2; ++n)
                        mma16816(c[m][n], a[m], bb[n]);
            }
        }

        #pragma unroll
        for (int m = 0; m < 2; ++m) {
            #pragma unroll
            for (int n = 0; n < 2; ++n) {
                int lrow = l0 + warpM * 32 + m * 16 + g;
                int vcol = v0 + warpN * 16 + n * 8 + t2;
                if (lrow < LP1) {
                    g_enc[(size_t)lrow * V_ + vcol]     = c[m][n][0] + We_b[vcol];
                    g_enc[(size_t)lrow * V_ + vcol + 1] = c[m][n][1] + We_b[vcol + 1];
                }
                if (lrow + 8 < LP1) {
                    g_enc[(size_t)(lrow + 8) * V_ + vcol]     = c[m][n][2] + We_b[vcol];
                    g_enc[(size_t)(lrow + 8) * V_ + vcol + 1] = c[m][n][3] + We_b[vcol + 1];
                }
            }
        }
        __syncthreads();
    }

    // =======================================================================
    // Prologue A: own 52 gate rows -> SMEM fp16
    // =======================================================================
    {
        const int n4 = JSM * 4 * (D_ / 4);
        for (int i = tid; i < n4; i += NT) {
            int rr = i >> 9;
            int k4 = i & 511;
            int lj = rr >> 2, gate = rr & 3;
            const float4* src = (const float4*)&W_hh[(size_t)(gate * D_ + b * JSM + lj) * D_] + k4;
            float4 v = *src;
            __half2 h01 = __floats2half2_rn(v.x, v.y);
            __half2 h23 = __floats2half2_rn(v.z, v.w);
            uint2 pk; pk.x = *(unsigned*)&h01; pk.y = *(unsigned*)&h23;
            ((uint2*)wsm)[(size_t)rr * 512 + k4] = pk;
        }
    }
    if (tid < 56) {
        int lj = tid >> 2, gate = tid & 3;
        int j = (lj < JSM) ? (b * JSM + lj) : (JL0 + b);
        if (lj < JSM || b < NJX) {
            int r = gate * D_ + j;
            pp[tid * 4 + 0] = b_ih[r] + b_hh[r];
            pp[tid * 4 + 1] = W_ih[r * 3 + 0];
            pp[tid * 4 + 2] = W_ih[r * 3 + 1];
            pp[tid * 4 + 3] = W_ih[r * 3 + 2];
        }
    }
    if (tid < T_) {
        float x0 = 0.f, x1 = 0.f, x2 = 1.f;
        if (tid >= 1) {
            int pos = positions[tid - 1];
            x0 = seq_points[pos * 3 + 0];
            x1 = seq_points[pos * 3 + 1];
            x2 = seq_points[pos * 3 + 2];
        }
        xs[tid * 4 + 0] = x0; xs[tid * 4 + 1] = x1; xs[tid * 4 + 2] = x2;
    }
    // Prologue B (blocks 80..147): Wd + leftover gate rows -> fp16 L2 buffers
    if (b >= 80) {
        const int nWd = V_ * (D_ / 4);
        const int nX  = NJX * 4 * (D_ / 4);
        for (int i = (b - 80) * NT + tid; i < nWd + nX; i += (NBLK - 80) * NT) {
            float4 v; uint2* dst;
            if (i < nWd) {
                v = ((const float4*)Wd_w)[i];
                dst = (uint2*)g_w16 + i;
            } else {
                int ii = i - nWd;
                int flat = ii >> 9;
                int k4 = ii & 511;
                int jj = flat >> 2, gate = flat & 3;
                v = *((const float4*)&W_hh[(size_t)(gate * D_ + JL0 + jj) * D_] + k4);
                dst = (uint2*)g_w16x + ii;
            }
            __half2 h01 = __floats2half2_rn(v.x, v.y);
            __half2 h23 = __floats2half2_rn(v.z, v.w);
            uint2 pk; pk.x = *(unsigned*)&h01; pk.y = *(unsigned*)&h23;
            *dst = pk;
        }
    }
    // Prologue C (blocks 0..79): poison h buffer only
    if (b < 80) {
        unsigned* hh = (unsigned*)g_hall;
        for (int i = b * NT + tid; i < T_ * D_; i += 80 * NT)
            hh[i] = CANARY;
    }

    hsm[tid]      = initial_state[tid];
    hsm[tid + NT] = initial_state[tid + NT];
    gridbar(++gen);

    // =======================================================================
    // Stage 1: 65 steps, h-value dataflow.
    //   warps 0..6 : 13 SMEM j's (wid<6: 2 each, wid6: 1)
    //   warps 8..11: leftover j (b<124): one gate row each from L2 (1 round)
    //   warps 12,13: shadow d-crew (d_{t-1} from hsm; zero polling)
    // =======================================================================
    {
        const int njs = (wid < 6) ? 2 : ((wid == 6) ? 1 : 0);
        const int lj0 = 2 * wid;
        float cst[2] = {0.f, 0.f};

        const bool isLW = (wid >= 8 && wid < 12 && b < NJX);
        const int  lgate = wid - 8;
        const uint4* lw4 = (const uint4*)g_w16x + ((size_t)b * 4 + (isLW ? lgate : 0)) * 256;
        float cleft = 0.f;

        const bool isDW = (wid == 12 || wid == 13);
        int vj[7]; int nd = 0;
        if (wid == 12) {
            nd = 7;
            #pragma unroll
            for (int r = 0; r < 7; ++r) vj[r] = b * JSM + r;
        } else if (wid == 13) {
            nd = (b < NJX) ? 7 : 6;
            #pragma unroll
            for (int r = 0; r < 6; ++r) vj[r] = b * JSM + 7 + r;
            vj[6] = (b < NJX) ? (JL0 + b) : 0;
        }
        float wdb[7];
        #pragma unroll
        for (int r = 0; r < 7; ++r) wdb[r] = (isDW && r < nd) ? Wd_b[vj[r]] : 0.f;

        for (int t = 0; t < T_; ++t) {
            const float4* h4 = (const float4*)hsm;
            const float x0 = xs[t * 4 + 0], x1 = xs[t * 4 + 1], x2 = xs[t * 4 + 2];

            if (njs) {
                #pragma unroll
                for (int jj = 0; jj < 2; ++jj) {
                    if (jj >= njs) break;
                    const int lj = lj0 + jj;
                    float acc[4] = {0.f, 0.f, 0.f, 0.f};
                    const uint4* w0 = (const uint4*)wsm + (size_t)(lj * 4) * 256;
                    #pragma unroll 2
                    for (int k8 = lane; k8 < 256; k8 += 32) {
                        float4 ha = h4[2 * k8];
                        float4 hb = h4[2 * k8 + 1];
                        acc[0] = dot8(w0[k8], ha, hb, acc[0]);
                        acc[1] = dot8(w0[256 + k8], ha, hb, acc[1]);
                        acc[2] = dot8(w0[512 + k8], ha, hb, acc[2]);
                        acc[3] = dot8(w0[768 + k8], ha, hb, acc[3]);
                    }
                    #pragma unroll
                    for (int off = 16; off > 0; off >>= 1) {
                        acc[0] += __shfl_xor_sync(0xffffffffu, acc[0], off);
                        acc[1] += __shfl_xor_sync(0xffffffffu, acc[1], off);
                        acc[2] += __shfl_xor_sync(0xffffffffu, acc[2], off);
                        acc[3] += __shfl_xor_sync(0xffffffffu, acc[3], off);
                    }
                    const int gsel = lane & 3;
                    const float* P = pp + (lj * 4 + gsel) * 4;
                    float e = P[0] + P[1] * x0 + P[2] * x1 + P[3] * x2;
                    float z = ((gsel == 0) ? acc[0] : (gsel == 1) ? acc[1]
                             : (gsel == 2) ? acc[2] : acc[3]) + e;
                    bool isG = (gsel == 2);
                    float arg = isG ? z : 0.5f * z;
                    float yt  = fast_tanh(arg);
                    float y   = isG ? yt : fmaf(0.5f, yt, 0.5f);
                    float i_ = __shfl_sync(0xffffffffu, y, 0);
                    float f_ = __shfl_sync(0xffffffffu, y, 1);
                    float g_ = __shfl_sync(0xffffffffu, y, 2);
                    float o_ = __shfl_sync(0xffffffffu, y, 3);
                    cst[jj] = fmaf(f_, cst[jj], i_ * g_);
                    float h = o_ * fast_tanh(cst[jj]);
                    if (lane == 0) {
                        asm volatile("st.global.cg.f32 [%0], %1;"
                            :: "l"(&g_hall[(size_t)t * D_ + b * JSM + lj]), "f"(h) : "memory");
                    }
                }
            } else if (isLW) {
                // one gate row of the leftover j per warp; single L2 round
                float acc = 0.f;
                #pragma unroll
                for (int i = 0; i < 8; ++i) {
                    int k8 = lane + (i << 5);
                    acc = dot8(__ldcg(lw4 + k8), h4[2 * k8], h4[2 * k8 + 1], acc);
                }
                #pragma unroll
                for (int off = 16; off > 0; off >>= 1)
                    acc += __shfl_xor_sync(0xffffffffu, acc, off);
                if (lane == 0) {
                    const float* P = pp + (52 + lgate) * 4;
                    red[lgate] = acc + P[0] + P[1] * x0 + P[2] * x1 + P[3] * x2;
                }
                asm volatile("bar.sync 4, 128;" ::: "memory");
                if (wid == 8) {
                    const int gsel = lane & 3;
                    float z = red[gsel];
                    bool isG = (gsel == 2);
                    float arg = isG ? z : 0.5f * z;
                    float yt  = fast_tanh(arg);
                    float y   = isG ? yt : fmaf(0.5f, yt, 0.5f);
                    float i_ = __shfl_sync(0xffffffffu, y, 0);
                    float f_ = __shfl_sync(0xffffffffu, y, 1);
                    float g_ = __shfl_sync(0xffffffffu, y, 2);
                    float o_ = __shfl_sync(0xffffffffu, y, 3);
                    cleft = fmaf(f_, cleft, i_ * g_);
                    float h = o_ * fast_tanh(cleft);
                    if (lane == 0) {
                        asm volatile("st.global.cg.f32 [%0], %1;"
                            :: "l"(&g_hall[(size_t)t * D_ + JL0 + b]), "f"(h) : "memory");
                    }
                }
            } else if (isDW && t >= 1) {
                // shadow: d_{t-1} from hsm (h_{t-1} is current hsm contents)
                float acc[7] = {0.f, 0.f, 0.f, 0.f, 0.f, 0.f, 0.f};
                #pragma unroll 2
                for (int i = 0; i < 16; ++i) {
                    int k4 = lane + (i << 5);
                    float4 h = h4[k4];
                    #pragma unroll
                    for (int r = 0; r < 7; ++r) {
                        if (r < nd) {
                            uint2 w = __ldcg((const uint2*)(g_w16 + (size_t)vj[r] * D_) + k4);
                            acc[r] = dot4h(w, h, acc[r]);
                        }
                    }
                }
                #pragma unroll
                for (int off = 16; off > 0; off >>= 1) {
                    #pragma unroll
                    for (int r = 0; r < 7; ++r)
                        acc[r] += __shfl_xor_sync(0xffffffffu, acc[r], off);
                }
                if (lane < nd) {
                    float v = acc[0];
                    if (lane == 1) v = acc[1];
                    if (lane == 2) v = acc[2];
                    if (lane == 3) v = acc[3];
                    if (lane == 4) v = acc[4];
                    if (lane == 5) v = acc[5];
                    if (lane == 6) v = acc[6];
                    float wb = wdb[0];
                    if (lane == 1) wb = wdb[1];
                    if (lane == 2) wb = wdb[2];
                    if (lane == 3) wb = wdb[3];
                    if (lane == 4) wb = wdb[4];
                    if (lane == 5) wb = wdb[5];
                    if (lane == 6) wb = wdb[6];
                    int v_ = vj[0];
                    if (lane == 1) v_ = vj[1];
                    if (lane == 2) v_ = vj[2];
                    if (lane == 3) v_ = vj[3];
                    if (lane == 4) v_ = vj[4];
                    if (lane == 5) v_ = vj[5];
                    if (lane == 6) v_ = vj[6];
                    __stcg(&g_dall[(size_t)(t - 1) * D_ + v_], v + wb);
                }
            }
            __syncthreads();      // hsm reads complete before gather overwrites

            // ---- gather h_t: poll own pair (value-carried sync) ----
            {
                const float* hb = g_hall + (size_t)t * D_ + 2 * tid;
                unsigned vx, vy;
                asm volatile("ld.global.cg.v2.u32 {%0,%1}, [%2];"
                             : "=r"(vx), "=r"(vy) : "l"(hb) : "memory");
                while (vx == CANARY || vy == CANARY) {
                    __nanosleep(32);
                    asm volatile("ld.global.cg.v2.u32 {%0,%1}, [%2];"
                                 : "=r"(vx), "=r"(vy) : "l"(hb) : "memory");
                }
                float fx = __uint_as_float(vx), fy = __uint_as_float(vy);
                hsm[2 * tid]     = fx;
                hsm[2 * tid + 1] = fy;
                if (b == t) {
                    out_hs[(size_t)t * D_ + 2 * tid]     = fx;
                    out_hs[(size_t)t * D_ + 2 * tid + 1] = fy;
                }
            }
            __syncthreads();      // hsm complete before next matvec
        }

        // post-loop: d_64 from final hsm
        if (isDW) {
            const float4* h4 = (const float4*)hsm;
            float acc[7] = {0.f, 0.f, 0.f, 0.f, 0.f, 0.f, 0.f};
            #pragma unroll 2
            for (int i = 0; i < 16; ++i) {
                int k4 = lane + (i << 5);
                float4 h = h4[k4];
                #pragma unroll
                for (int r = 0; r < 7; ++r) {
                    if (r < nd) {
                        uint2 w = __ldcg((const uint2*)(g_w16 + (size_t)vj[r] * D_) + k4);
                        acc[r] = dot4h(w, h, acc[r]);
                    }
                }
            }
            #pragma unroll
            for (int off = 16; off > 0; off >>= 1) {
                #pragma unroll
                for (int r = 0; r < 7; ++r)
                    acc[r] += __shfl_xor_sync(0xffffffffu, acc[r], off);
            }
            if (lane < nd) {
                float v = acc[0];
                if (lane == 1) v = acc[1];
                if (lane == 2) v = acc[2];
                if (lane == 3) v = acc[3];
                if (lane == 4) v = acc[4];
                if (lane == 5) v = acc[5];
                if (lane == 6) v = acc[6];
                float wb = wdb[0];
                if (lane == 1) wb = wdb[1];
                if (lane == 2) wb = wdb[2];
                if (lane == 3) wb = wdb[3];
                if (lane == 4) wb = wdb[4];
                if (lane == 5) wb = wdb[5];
                if (lane == 6) wb = wdb[6];
                int v_ = vj[0];
                if (lane == 1) v_ = vj[1];
                if (lane == 2) v_ = vj[2];
                if (lane == 3) v_ = vj[3];
                if (lane == 4) v_ = vj[4];
                if (lane == 5) v_ = vj[5];
                if (lane == 6) v_ = vj[6];
                __stcg(&g_dall[(size_t)64 * D_ + v_], v + wb);
            }
        }
    }

    gridbar(++gen);     // all h and d published

    // =======================================================================
    // Stage 2: logits[t][l] = sum_v tanh(enc[l][v] + d_t[v]) * v_w[v] + v_b
    // =======================================================================
    float* sd  = (float*)dynsm;
    float* svw = (float*)(dynsm + D_ * 4);
    for (int j = tid; j < V_; j += NT) svw[j] = v_w[j];
    const float vb = v_b[0];

    for (int item = b; item < T_ * 9; item += NBLK) {
        const int t  = item / 9;
        const int ch = item % 9;
        __syncthreads();
        for (int j = tid; j < V_; j += NT)
            sd[j] = __ldcg(&g_dall[(size_t)t * D_ + j]);
        __syncthreads();

        const int lbase = ch * 57;
        const float4* d4 = (const float4*)sd;
        const float4* w4 = (const float4*)svw;
        for (int l = lbase + wid; l < lbase + 57; l += NW) {
            const float4* e4 = (const float4*)(g_enc + (size_t)l * V_);
            float acc = 0.f;
            #pragma unroll 2
            for (int k = lane; k < V_ / 4; k += 32) {
                float4 e = __ldcg(e4 + k);
                float4 d = d4[k];
                float4 w = w4[k];
                acc = fmaf(hw_tanh(e.x + d.x), w.x, acc);
                acc = fmaf(hw_tanh(e.y + d.y), w.y, acc);
                acc = fmaf(hw_tanh(e.z + d.z), w.z, acc);
                acc = fmaf(hw_tanh(e.w + d.w), w.w, acc);
            }
            #pragma unroll
            for (int off = 16; off > 0; off >>= 1)
                acc += __shfl_down_sync(0xffffffffu, acc, off);
            if (lane == 0) __stcg(&out_logits[(size_t)t * LP1 + l], acc + vb);
        }
    }

    gridbar(++gen);

    // =======================================================================
    // Stage 3: losses
    // =======================================================================
    if (b < T_) {
        const int t = b;
        const float* lg = out_logits + (size_t)t * LP1;

        float m = -1e30f;
        for (int i = tid; i < LP1; i += NT) m = fmaxf(m, __ldcg(lg + i));
        #pragma unroll
        for (int off = 16; off > 0; off >>= 1)
            m = fmaxf(m, __shfl_down_sync(0xffffffffu, m, off));
        if (lane == 0) red[wid] = m;
        __syncthreads();
        if (wid == 0) {
            float mm = (lane < NW) ? red[lane] : -1e30f;
            #pragma unroll
            for (int off = 16; off > 0; off >>= 1)
                mm = fmaxf(mm, __shfl_down_sync(0xffffffffu, mm, off));
            if (lane == 0) red[0] = mm;
        }
        __syncthreads();
        m = red[0];
        __syncthreads();

        float s = 0.f;
        for (int i = tid; i < LP1; i += NT) s += expf(__ldcg(lg + i) - m);
        #pragma unroll
        for (int off = 16; off > 0; off >>= 1)
            s += __shfl_down_sync(0xffffffffu, s, off);
        if (lane == 0) red[wid] = s;
        __syncthreads();
        if (wid == 0) {
            float ss = (lane < NW) ? red[lane] : 0.f;
            #pragma unroll
            for (int off = 16; off > 0; off >>= 1)
                ss += __shfl_down_sync(0xffffffffu, ss, off);
            if (lane == 0) {
                int tgt = (t < 64) ? positions[t] : LSEQ;
                out_losses[t] = m + logf(ss) - __ldcg(lg + tgt);
            }
        }
    }
}

// ---------------------------------------------------------------------------
extern "C" void kernel_launch(void* const* d_in, const int* in_sizes, int n_in,
                              void* d_out, int out_size) {
    const float* initial_state = (const float*)d_in[0];
    const float* enc_states    = (const float*)d_in[1];
    const float* seq_points    = (const float*)d_in[2];
    const int*   positions     = (const int*)  d_in[3];
    const float* W_ih          = (const float*)d_in[4];
    const float* W_hh          = (const float*)d_in[5];
    const float* b_ih          = (const float*)d_in[6];
    const float* b_hh          = (const float*)d_in[7];
    const float* We_w          = (const float*)d_in[8];
    const float* We_b          = (const float*)d_in[9];
    const float* Wd_w          = (const float*)d_in[10];
    const float* Wd_b          = (const float*)d_in[11];
    const float* v_w           = (const float*)d_in[12];
    const float* v_b           = (const float*)d_in[13];

    float* out        = (float*)d_out;
    float* out_logits = out;
    float* out_hs     = out + T_ * LP1;
    float* out_losses = out + T_ * LP1 + T_ * D_;

    static int smem_set = 0;
    if (!smem_set) {
        cudaFuncSetAttribute(decoder_kernel,
                             cudaFuncAttributeMaxDynamicSharedMemorySize, SMEM_BYTES);
        smem_set = 1;
    }

    decoder_kernel<<<NBLK, NT, SMEM_BYTES>>>(
        initial_state, enc_states, seq_points, positions,
        W_ih, W_hh, b_ih, b_hh, We_w, We_b, Wd_w, Wd_b,
        v_w, v_b, out_logits, out_hs, out_losses);
}